// round 5
// baseline (speedup 1.0000x reference)
#include <cuda_runtime.h>
#include <cuda_bf16.h>
#include <math.h>
#include <stdint.h>

#define T_   64
#define B_   512
#define D_   768
#define H_   12
#define HD_  64
#define E3_  2304
#define NROWS (T_*B_)

// scratch
__device__ __align__(256) float g_out[(size_t)NROWS * D_];
__device__ __align__(256) float g_mean[T_ * D_];
__device__ __align__(256) __nv_bfloat16 g_qkv_hi[(size_t)NROWS * E3_], g_qkv_lo[(size_t)NROWS * E3_];
__device__ __align__(256) __nv_bfloat16 g_node_hi[(size_t)NROWS * D_], g_node_lo[(size_t)NROWS * D_];
__device__ __align__(256) __nv_bfloat16 g_ctx_hi [(size_t)NROWS * D_], g_ctx_lo [(size_t)NROWS * D_];
__device__ __align__(256) __nv_bfloat16 g_w1_hi[(size_t)E3_ * D_], g_w1_lo[(size_t)E3_ * D_];
__device__ __align__(256) __nv_bfloat16 g_w2_hi[(size_t)D_ * D_],  g_w2_lo[(size_t)D_ * D_];

__device__ __forceinline__ uint32_t smem_u32(const void* p) {
    uint32_t a;
    asm("{ .reg .u64 t; cvta.to.shared.u64 t, %1; cvt.u32.u64 %0, t; }" : "=r"(a) : "l"(p));
    return a;
}
__device__ __forceinline__ void cp_async16(uint32_t s, const void* g) {
    asm volatile("cp.async.cg.shared.global [%0], [%1], 16;" :: "r"(s), "l"(g) : "memory");
}
__device__ __forceinline__ void cp_commit() { asm volatile("cp.async.commit_group;" ::: "memory"); }
__device__ __forceinline__ void cp_wait1()  { asm volatile("cp.async.wait_group 1;" ::: "memory"); }
__device__ __forceinline__ void cp_wait0()  { asm volatile("cp.async.wait_group 0;" ::: "memory"); }
__device__ __forceinline__ void ldsm4(uint32_t* r, uint32_t addr) {
    asm volatile("ldmatrix.sync.aligned.m8n8.x4.shared.b16 {%0,%1,%2,%3}, [%4];"
                 : "=r"(r[0]), "=r"(r[1]), "=r"(r[2]), "=r"(r[3]) : "r"(addr));
}
__device__ __forceinline__ void mma16816(float* d, const uint32_t* a, uint32_t b0, uint32_t b1) {
    asm volatile(
        "mma.sync.aligned.m16n8k16.row.col.f32.bf16.bf16.f32 "
        "{%0,%1,%2,%3}, {%4,%5,%6,%7}, {%8,%9}, {%0,%1,%2,%3};"
        : "+f"(d[0]), "+f"(d[1]), "+f"(d[2]), "+f"(d[3])
        : "r"(a[0]), "r"(a[1]), "r"(a[2]), "r"(a[3]), "r"(b0), "r"(b1));
}
__device__ __forceinline__ uint32_t pack_bf16x2(float a, float b) {
    __nv_bfloat162 h = __floats2bfloat162_rn(a, b);
    return *reinterpret_cast<uint32_t*>(&h);
}

// ---------------------------------------------------------------------------
// fp32 -> (hi, lo) bf16 split (inputs only: node, w1, w2)
// ---------------------------------------------------------------------------
__global__ __launch_bounds__(256) void split_kernel(
    const float4* __restrict__ x, __nv_bfloat162* __restrict__ hi,
    __nv_bfloat162* __restrict__ lo, int n4)
{
    int i = blockIdx.x * 256 + threadIdx.x;
    if (i >= n4) return;
    float4 v = x[i];
    __nv_bfloat16 h0 = __float2bfloat16(v.x), h1 = __float2bfloat16(v.y);
    __nv_bfloat16 h2 = __float2bfloat16(v.z), h3 = __float2bfloat16(v.w);
    hi[2*i]   = __nv_bfloat162(h0, h1);
    hi[2*i+1] = __nv_bfloat162(h2, h3);
    lo[2*i]   = __nv_bfloat162(__float2bfloat16(v.x - __bfloat162float(h0)),
                               __float2bfloat16(v.y - __bfloat162float(h1)));
    lo[2*i+1] = __nv_bfloat162(__float2bfloat16(v.z - __bfloat162float(h2)),
                               __float2bfloat16(v.w - __bfloat162float(h3)));
}

// ---------------------------------------------------------------------------
// mma.sync split-bf16 GEMM, now 2 CTAs/SM (the round-5 change).
// ---------------------------------------------------------------------------
#define RS   80
#define TOFF 10240
#define SOFF 40960

__global__ __launch_bounds__(256, 2) void gemm_mma_split(
    const __nv_bfloat16* __restrict__ Ahi, const __nv_bfloat16* __restrict__ Alo,
    const __nv_bfloat16* __restrict__ Bhi, const __nv_bfloat16* __restrict__ Blo,
    const float* __restrict__ bias, float* __restrict__ C,
    __nv_bfloat16* __restrict__ Chi, __nv_bfloat16* __restrict__ Clo,
    int N, int do_split, int scale_cols)
{
    extern __shared__ char smem[];
    const uint32_t sb = smem_u32(smem);
    const int tid = threadIdx.x;
    const int wid = tid >> 5, lane = tid & 31;
    const int wm = wid & 1, wn = wid >> 1;
    const int m0 = blockIdx.y * 128;
    const int n0 = blockIdx.x * 128;

    const __nv_bfloat16* srcs[4] = {Ahi, Alo, Bhi, Blo};
    const int r0s[4] = {m0, m0, n0, n0};
    const int crow = tid >> 2;
    const int cc4  = tid & 3;

    float acc[4][4][4] = {};

    const int lrow  = ((lane >> 3) & 1) * 8 + (lane & 7);
    const int lkoff = (lane >> 4) * 16;
    const uint32_t a_base = sb + (uint32_t)(wm * 64 + lrow) * RS + lkoff;
    const uint32_t b_base = sb + (uint32_t)(wn * 32 + lrow) * RS + lkoff;

    {
        #pragma unroll
        for (int tI = 0; tI < 4; ++tI)
            #pragma unroll
            for (int it = 0; it < 2; ++it) {
                int row = crow + it * 64;
                cp_async16(sb + tI * TOFF + row * RS + cc4 * 16,
                           srcs[tI] + (size_t)(r0s[tI] + row) * D_ + cc4 * 8);
            }
        cp_commit();
    }

    for (int c = 0; c < 24; ++c) {
        if (c < 23) {
            const int k0 = (c + 1) * 32;
            const uint32_t base = sb + ((c + 1) & 1) * SOFF;
            #pragma unroll
            for (int tI = 0; tI < 4; ++tI)
                #pragma unroll
                for (int it = 0; it < 2; ++it) {
                    int row = crow + it * 64;
                    cp_async16(base + tI * TOFF + row * RS + cc4 * 16,
                               srcs[tI] + (size_t)(r0s[tI] + row) * D_ + k0 + cc4 * 8);
                }
            cp_commit();
            cp_wait1();
        } else {
            cp_wait0();
        }
        __syncthreads();

        const uint32_t st = ((uint32_t)(c & 1)) * SOFF;
        #pragma unroll
        for (int ks = 0; ks < 2; ++ks) {
            const uint32_t ko = ks * 32;
            uint32_t ah[4][4], al[4][4], bh[2][4], bl[2][4];
            #pragma unroll
            for (int mi = 0; mi < 4; ++mi) {
                ldsm4(ah[mi], a_base + st + 0 * TOFF + mi * 16 * RS + ko);
                ldsm4(al[mi], a_base + st + 1 * TOFF + mi * 16 * RS + ko);
            }
            #pragma unroll
            for (int nt = 0; nt < 2; ++nt) {
                ldsm4(bh[nt], b_base + st + 2 * TOFF + nt * 16 * RS + ko);
                ldsm4(bl[nt], b_base + st + 3 * TOFF + nt * 16 * RS + ko);
            }
            #pragma unroll
            for (int mi = 0; mi < 4; ++mi)
                #pragma unroll
                for (int ni = 0; ni < 4; ++ni) {
                    const int nt = ni >> 1, hl = ni & 1;
                    mma16816(acc[mi][ni], ah[mi], bh[nt][hl], bh[nt][hl + 2]);
                    mma16816(acc[mi][ni], ah[mi], bl[nt][hl], bl[nt][hl + 2]);
                    mma16816(acc[mi][ni], al[mi], bh[nt][hl], bh[nt][hl + 2]);
                }
        }
        __syncthreads();
    }

    const int g   = lane >> 2;
    const int tig = lane & 3;
    #pragma unroll
    for (int mi = 0; mi < 4; ++mi) {
        const int row = m0 + wm * 64 + mi * 16 + g;
        #pragma unroll
        for (int ni = 0; ni < 4; ++ni) {
            const int col = n0 + wn * 32 + ni * 8 + tig * 2;
            float b0v = bias[col], b1v = bias[col + 1];
            float v00 = acc[mi][ni][0] + b0v, v01 = acc[mi][ni][1] + b1v;
            float v10 = acc[mi][ni][2] + b0v, v11 = acc[mi][ni][3] + b1v;
            if (do_split) {
                float sc = (col < scale_cols) ? 0.125f : 1.0f;
                v00 *= sc; v01 *= sc; v10 *= sc; v11 *= sc;
                uint32_t h0 = pack_bf16x2(v00, v01);
                uint32_t h1 = pack_bf16x2(v10, v11);
                __nv_bfloat162 h0b = *reinterpret_cast<__nv_bfloat162*>(&h0);
                __nv_bfloat162 h1b = *reinterpret_cast<__nv_bfloat162*>(&h1);
                uint32_t l0 = pack_bf16x2(v00 - __bfloat162float(h0b.x), v01 - __bfloat162float(h0b.y));
                uint32_t l1 = pack_bf16x2(v10 - __bfloat162float(h1b.x), v11 - __bfloat162float(h1b.y));
                *reinterpret_cast<uint32_t*>(&Chi[(size_t)row * N + col]) = h0;
                *reinterpret_cast<uint32_t*>(&Chi[(size_t)(row + 8) * N + col]) = h1;
                *reinterpret_cast<uint32_t*>(&Clo[(size_t)row * N + col]) = l0;
                *reinterpret_cast<uint32_t*>(&Clo[(size_t)(row + 8) * N + col]) = l1;
            } else {
                float2 va = {v00, v01}, vb = {v10, v11};
                *reinterpret_cast<float2*>(&C[(size_t)row * N + col]) = va;
                *reinterpret_cast<float2*>(&C[(size_t)(row + 8) * N + col]) = vb;
            }
        }
    }
}

// ---------------------------------------------------------------------------
// Tensor-core flash attention over the B axis (unchanged from round 4)
// ---------------------------------------------------------------------------
#define ARS 144

__global__ __launch_bounds__(256) void attn_mma_kernel()
{
    extern __shared__ char smem[];
    const uint32_t sb = smem_u32(smem);
    const int tid = threadIdx.x, lane = tid & 31, wid = tid >> 5;
    const int qt = blockIdx.x, h = blockIdx.y, t = blockIdx.z;
    const int q0 = qt * 128;
    const size_t trow = (size_t)t * B_;

    const __nv_bfloat16* qhg = g_qkv_hi + (trow + q0) * E3_ + h * HD_;
    const __nv_bfloat16* qlg = g_qkv_lo + (trow + q0) * E3_ + h * HD_;
    const __nv_bfloat16* khg0 = g_qkv_hi + trow * E3_ + D_ + h * HD_;
    const __nv_bfloat16* klg0 = g_qkv_lo + trow * E3_ + D_ + h * HD_;
    const __nv_bfloat16* vhg0 = g_qkv_hi + trow * E3_ + 2 * D_ + h * HD_;
    const __nv_bfloat16* vlg0 = g_qkv_lo + trow * E3_ + 2 * D_ + h * HD_;

    const int QH = 0, QL = 128 * ARS;
    const int KH = 0, KL = 64 * ARS, VH = 2 * 64 * ARS, VL = 3 * 64 * ARS;

    #pragma unroll
    for (int it = 0; it < 4; ++it) {
        int f = it * 256 + tid, r = f >> 3, c = f & 7;
        *(float4*)(smem + QH + r * ARS + c * 16) = *(const float4*)(qhg + (size_t)r * E3_ + c * 8);
        *(float4*)(smem + QL + r * ARS + c * 16) = *(const float4*)(qlg + (size_t)r * E3_ + c * 8);
    }
    __syncthreads();

    const int lrow  = ((lane >> 3) & 1) * 8 + (lane & 7);
    const int lkoff = (lane >> 4) * 16;
    uint32_t qfh[4][4], qfl[4][4];
    {
        const uint32_t qa = sb + (uint32_t)(wid * 16 + lrow) * ARS + lkoff;
        #pragma unroll
        for (int ks = 0; ks < 4; ++ks) {
            ldsm4(qfh[ks], qa + QH + ks * 32);
            ldsm4(qfl[ks], qa + QL + ks * 32);
        }
    }
    __syncthreads();

    float oacc[8][4] = {};
    float mr0 = -1e30f, mr1 = -1e30f, lr0 = 0.f, lr1 = 0.f;

    for (int kt = 0; kt < 8; ++kt) {
        const __nv_bfloat16* khg = khg0 + (size_t)kt * 64 * E3_;
        const __nv_bfloat16* klg = klg0 + (size_t)kt * 64 * E3_;
        const __nv_bfloat16* vhg = vhg0 + (size_t)kt * 64 * E3_;
        const __nv_bfloat16* vlg = vlg0 + (size_t)kt * 64 * E3_;

        #pragma unroll
        for (int it = 0; it < 2; ++it) {
            int f = it * 256 + tid, r = f >> 3, c = f & 7;
            *(float4*)(smem + KH + r * ARS + c * 16) = *(const float4*)(khg + (size_t)r * E3_ + c * 8);
            *(float4*)(smem + KL + r * ARS + c * 16) = *(const float4*)(klg + (size_t)r * E3_ + c * 8);
        }
        #pragma unroll
        for (int it = 0; it < 4; ++it) {
            int idx = it * 256 + tid, s = idx & 31, c = idx >> 5;
            uint32_t u0 = *(const uint32_t*)(vhg + (size_t)(2 * s) * E3_ + 2 * c);
            uint32_t u1 = *(const uint32_t*)(vhg + (size_t)(2 * s + 1) * E3_ + 2 * c);
            *(uint32_t*)(smem + VH + (2 * c) * ARS + s * 4)     = (u0 & 0xFFFFu) | (u1 << 16);
            *(uint32_t*)(smem + VH + (2 * c + 1) * ARS + s * 4) = (u0 >> 16) | (u1 & 0xFFFF0000u);
            u0 = *(const uint32_t*)(vlg + (size_t)(2 * s) * E3_ + 2 * c);
            u1 = *(const uint32_t*)(vlg + (size_t)(2 * s + 1) * E3_ + 2 * c);
            *(uint32_t*)(smem + VL + (2 * c) * ARS + s * 4)     = (u0 & 0xFFFFu) | (u1 << 16);
            *(uint32_t*)(smem + VL + (2 * c + 1) * ARS + s * 4) = (u0 >> 16) | (u1 & 0xFFFF0000u);
        }
        __syncthreads();

        float sacc[8][4] = {};
        #pragma unroll
        for (int ks = 0; ks < 4; ++ks) {
            uint32_t kfh[4][4], kfl[4][4];
            #pragma unroll
            for (int ng = 0; ng < 4; ++ng) {
                const uint32_t ka = sb + (uint32_t)(ng * 16 + lrow) * ARS + lkoff + ks * 32;
                ldsm4(kfh[ng], ka + KH);
                ldsm4(kfl[ng], ka + KL);
            }
            #pragma unroll
            for (int ng = 0; ng < 4; ++ng)
                #pragma unroll
                for (int sub = 0; sub < 2; ++sub) {
                    const int ni = ng * 2 + sub;
                    mma16816(sacc[ni], qfh[ks], kfh[ng][sub], kfh[ng][sub + 2]);
                    mma16816(sacc[ni], qfh[ks], kfl[ng][sub], kfl[ng][sub + 2]);
                    mma16816(sacc[ni], qfl[ks], kfh[ng][sub], kfh[ng][sub + 2]);
                }
        }

        float mx0 = -1e30f, mx1 = -1e30f;
        #pragma unroll
        for (int ni = 0; ni < 8; ++ni) {
            mx0 = fmaxf(mx0, fmaxf(sacc[ni][0], sacc[ni][1]));
            mx1 = fmaxf(mx1, fmaxf(sacc[ni][2], sacc[ni][3]));
        }
        mx0 = fmaxf(mx0, __shfl_xor_sync(0xffffffffu, mx0, 1));
        mx0 = fmaxf(mx0, __shfl_xor_sync(0xffffffffu, mx0, 2));
        mx1 = fmaxf(mx1, __shfl_xor_sync(0xffffffffu, mx1, 1));
        mx1 = fmaxf(mx1, __shfl_xor_sync(0xffffffffu, mx1, 2));
        const float nm0 = fmaxf(mr0, mx0), nm1 = fmaxf(mr1, mx1);
        const float a0 = __expf(mr0 - nm0), a1 = __expf(mr1 - nm1);
        mr0 = nm0; mr1 = nm1;

        uint32_t phA[8], phB[8], plA[8], plB[8];
        float rs0 = 0.f, rs1 = 0.f;
        #pragma unroll
        for (int ni = 0; ni < 8; ++ni) {
            float e0 = __expf(sacc[ni][0] - nm0), e1 = __expf(sacc[ni][1] - nm0);
            float e2 = __expf(sacc[ni][2] - nm1), e3 = __expf(sacc[ni][3] - nm1);
            rs0 += e0 + e1; rs1 += e2 + e3;
            uint32_t hA = pack_bf16x2(e0, e1), hB = pack_bf16x2(e2, e3);
            __nv_bfloat162 hAb = *reinterpret_cast<__nv_bfloat162*>(&hA);
            __nv_bfloat162 hBb = *reinterpret_cast<__nv_bfloat162*>(&hB);
            phA[ni] = hA; phB[ni] = hB;
            plA[ni] = pack_bf16x2(e0 - __bfloat162float(hAb.x), e1 - __bfloat162float(hAb.y));
            plB[ni] = pack_bf16x2(e2 - __bfloat162float(hBb.x), e3 - __bfloat162float(hBb.y));
            oacc[ni][0] *= a0; oacc[ni][1] *= a0;
            oacc[ni][2] *= a1; oacc[ni][3] *= a1;
        }
        rs0 += __shfl_xor_sync(0xffffffffu, rs0, 1);
        rs0 += __shfl_xor_sync(0xffffffffu, rs0, 2);
        rs1 += __shfl_xor_sync(0xffffffffu, rs1, 1);
        rs1 += __shfl_xor_sync(0xffffffffu, rs1, 2);
        lr0 = lr0 * a0 + rs0;
        lr1 = lr1 * a1 + rs1;

        #pragma unroll
        for (int j = 0; j < 4; ++j) {
            uint32_t vfh[4][4], vfl[4][4];
            #pragma unroll
            for (int ng = 0; ng < 4; ++ng) {
                const uint32_t va = sb + (uint32_t)(ng * 16 + lrow) * ARS + lkoff + j * 32;
                ldsm4(vfh[ng], va + VH);
                ldsm4(vfl[ng], va + VL);
            }
            uint32_t aph[4] = {phA[2*j], phB[2*j], phA[2*j+1], phB[2*j+1]};
            uint32_t apl[4] = {plA[2*j], plB[2*j], plA[2*j+1], plB[2*j+1]};
            #pragma unroll
            for (int ng = 0; ng < 4; ++ng)
                #pragma unroll
                for (int sub = 0; sub < 2; ++sub) {
                    const int ni = ng * 2 + sub;
                    mma16816(oacc[ni], aph, vfh[ng][sub], vfh[ng][sub + 2]);
                    mma16816(oacc[ni], aph, vfl[ng][sub], vfl[ng][sub + 2]);
                    mma16816(oacc[ni], apl, vfh[ng][sub], vfh[ng][sub + 2]);
                }
        }
        __syncthreads();
    }

    const float inv0 = 1.f / lr0, inv1 = 1.f / lr1;
    const int r0 = q0 + wid * 16 + (lane >> 2);
    const int col0 = h * HD_ + (lane & 3) * 2;
    __nv_bfloat16* chg = g_ctx_hi + (trow + r0) * D_ + col0;
    __nv_bfloat16* clg = g_ctx_lo + (trow + r0) * D_ + col0;
    #pragma unroll
    for (int ni = 0; ni < 8; ++ni) {
        float v0 = oacc[ni][0] * inv0, v1 = oacc[ni][1] * inv0;
        float v2 = oacc[ni][2] * inv1, v3 = oacc[ni][3] * inv1;
        uint32_t h0 = pack_bf16x2(v0, v1), h1 = pack_bf16x2(v2, v3);
        __nv_bfloat162 h0b = *reinterpret_cast<__nv_bfloat162*>(&h0);
        __nv_bfloat162 h1b = *reinterpret_cast<__nv_bfloat162*>(&h1);
        uint32_t l0 = pack_bf16x2(v0 - __bfloat162float(h0b.x), v1 - __bfloat162float(h0b.y));
        uint32_t l1 = pack_bf16x2(v2 - __bfloat162float(h1b.x), v3 - __bfloat162float(h1b.y));
        *reinterpret_cast<uint32_t*>(chg + ni * 8) = h0;
        *reinterpret_cast<uint32_t*>(chg + 8 * D_ + ni * 8) = h1;
        *reinterpret_cast<uint32_t*>(clg + ni * 8) = l0;
        *reinterpret_cast<uint32_t*>(clg + 8 * D_ + ni * 8) = l1;
    }
}

// ---------------------------------------------------------------------------
// Epilogue reductions
// ---------------------------------------------------------------------------
__device__ __forceinline__ float block_reduce_sum(float v, float* sbuf)
{
    int lane = threadIdx.x & 31, w = threadIdx.x >> 5;
    #pragma unroll
    for (int o = 16; o; o >>= 1) v += __shfl_xor_sync(0xffffffffu, v, o);
    if (lane == 0) sbuf[w] = v;
    __syncthreads();
    float s = (threadIdx.x < (blockDim.x >> 5)) ? sbuf[threadIdx.x] : 0.f;
    if (w == 0) {
        #pragma unroll
        for (int o = 4; o; o >>= 1) s += __shfl_xor_sync(0xffffffffu, s, o);
        if (lane == 0) sbuf[0] = s;
    }
    __syncthreads();
    return sbuf[0];
}

__global__ __launch_bounds__(256) void normalize_kernel()
{
    __shared__ float sbuf[32];
    int row = blockIdx.x;
    float* x = g_out + (size_t)row * D_;
    float s = 0.f;
    for (int i = threadIdx.x; i < D_; i += 256) { float v = x[i]; s += v * v; }
    s = block_reduce_sum(s, sbuf);
    float inv = 1.f / fmaxf(sqrtf(s), 1e-8f);
    for (int i = threadIdx.x; i < D_; i += 256) x[i] *= inv;
}

__global__ __launch_bounds__(256) void mean_kernel()
{
    int t = blockIdx.y;
    int d = blockIdx.x * 256 + threadIdx.x;
    const float* base = g_out + (size_t)t * B_ * D_ + d;
    float s = 0.f;
    for (int b = 0; b < B_; ++b) s += base[(size_t)b * D_];
    g_mean[t * D_ + d] = s * (1.f / B_);
}

__global__ __launch_bounds__(256) void adj_kernel(float* __restrict__ outp)
{
    __shared__ float sbuf[32];
    int row = blockIdx.x;
    int t = row / B_;
    const float* x = g_out + (size_t)row * D_;
    const float* m = g_mean + t * D_;
    float s = 0.f;
    for (int i = threadIdx.x; i < D_; i += 256) s += x[i] * m[i];
    s = block_reduce_sum(s, sbuf);
    if (threadIdx.x == 0) outp[row] = s;
}

// ---------------------------------------------------------------------------

extern "C" void kernel_launch(void* const* d_in, const int* in_sizes, int n_in,
                              void* d_out, int out_size)
{
    const float* node = (const float*)d_in[0];
    const float* w1   = (const float*)d_in[1];
    const float* b1   = (const float*)d_in[2];
    const float* w2   = (const float*)d_in[3];
    const float* b2   = (const float*)d_in[4];
    float* outp = (float*)d_out;

    float* outb;
    cudaGetSymbolAddress((void**)&outb, g_out);
    __nv_bfloat16 *qh, *ql, *nh, *nl, *ch, *cl, *w1h, *w1l, *w2h, *w2l;
    cudaGetSymbolAddress((void**)&qh,  g_qkv_hi);
    cudaGetSymbolAddress((void**)&ql,  g_qkv_lo);
    cudaGetSymbolAddress((void**)&nh,  g_node_hi);
    cudaGetSymbolAddress((void**)&nl,  g_node_lo);
    cudaGetSymbolAddress((void**)&ch,  g_ctx_hi);
    cudaGetSymbolAddress((void**)&cl,  g_ctx_lo);
    cudaGetSymbolAddress((void**)&w1h, g_w1_hi);
    cudaGetSymbolAddress((void**)&w1l, g_w1_lo);
    cudaGetSymbolAddress((void**)&w2h, g_w2_hi);
    cudaGetSymbolAddress((void**)&w2l, g_w2_lo);

    const int gemm_smem = 2 * SOFF;            // 80 KB
    const int attn_smem = 2 * 128 * ARS;       // 36864 B
    cudaFuncSetAttribute(gemm_mma_split, cudaFuncAttributeMaxDynamicSharedMemorySize, gemm_smem);
    cudaFuncSetAttribute(attn_mma_kernel, cudaFuncAttributeMaxDynamicSharedMemorySize, attn_smem);

    // split inputs
    {
        int n4 = NROWS * D_ / 4;
        split_kernel<<<(n4 + 255)/256, 256>>>((const float4*)node,
            (__nv_bfloat162*)nh, (__nv_bfloat162*)nl, n4);
        int w14 = E3_ * D_ / 4;
        split_kernel<<<(w14 + 255)/256, 256>>>((const float4*)w1,
            (__nv_bfloat162*)w1h, (__nv_bfloat162*)w1l, w14);
        int w24 = D_ * D_ / 4;
        split_kernel<<<(w24 + 255)/256, 256>>>((const float4*)w2,
            (__nv_bfloat162*)w2h, (__nv_bfloat162*)w2l, w24);
    }

    // 1. QKV projection -> bf16 hi/lo qkv (q cols pre-scaled by 0.125)
    gemm_mma_split<<<dim3(E3_/128, NROWS/128), 256, gemm_smem>>>(
        nh, nl, w1h, w1l, b1, nullptr, qh, ql, E3_, 1, D_);

    // 2. Tensor-core flash attention -> ctx bf16 hi/lo
    attn_mma_kernel<<<dim3(B_/128, H_, T_), 256, attn_smem>>>();

    // 3. Out projection -> fp32 g_out
    gemm_mma_split<<<dim3(D_/128, NROWS/128), 256, gemm_smem>>>(
        ch, cl, w2h, w2l, b2, outb, nullptr, nullptr, D_, 0, 0);

    // 4. Epilogue
    normalize_kernel<<<NROWS, 256>>>();
    mean_kernel<<<dim3(D_/256, T_), 256>>>();
    adj_kernel<<<NROWS, 256>>>(outp);
}

// round 6
// speedup vs baseline: 1.6382x; 1.6382x over previous
#include <cuda_runtime.h>
#include <cuda_fp16.h>
#include <math.h>
#include <stdint.h>

#define T_   64
#define B_   512
#define D_   768
#define H_   12
#define HD_  64
#define E3_  2304
#define NROWS (T_*B_)

// scratch
__device__ __align__(256) float g_out[(size_t)NROWS * D_];
__device__ __align__(256) float g_mean[T_ * D_];
__device__ __align__(256) __half g_qkv_hi[(size_t)NROWS * E3_], g_qkv_lo[(size_t)NROWS * E3_];
__device__ __align__(256) __half g_node_hi[(size_t)NROWS * D_], g_node_lo[(size_t)NROWS * D_];
__device__ __align__(256) __half g_ctx_hi [(size_t)NROWS * D_], g_ctx_lo [(size_t)NROWS * D_];
__device__ __align__(256) __half g_w1_hi[(size_t)E3_ * D_];
__device__ __align__(256) __half g_w2_hi[(size_t)D_ * D_];

__device__ __forceinline__ uint32_t smem_u32(const void* p) {
    uint32_t a;
    asm("{ .reg .u64 t; cvta.to.shared.u64 t, %1; cvt.u32.u64 %0, t; }" : "=r"(a) : "l"(p));
    return a;
}
__device__ __forceinline__ void cp_async16(uint32_t s, const void* g) {
    asm volatile("cp.async.cg.shared.global [%0], [%1], 16;" :: "r"(s), "l"(g) : "memory");
}
__device__ __forceinline__ void cp_commit() { asm volatile("cp.async.commit_group;" ::: "memory"); }
__device__ __forceinline__ void cp_wait1()  { asm volatile("cp.async.wait_group 1;" ::: "memory"); }
__device__ __forceinline__ void cp_wait0()  { asm volatile("cp.async.wait_group 0;" ::: "memory"); }
__device__ __forceinline__ void ldsm4(uint32_t* r, uint32_t addr) {
    asm volatile("ldmatrix.sync.aligned.m8n8.x4.shared.b16 {%0,%1,%2,%3}, [%4];"
                 : "=r"(r[0]), "=r"(r[1]), "=r"(r[2]), "=r"(r[3]) : "r"(addr));
}
__device__ __forceinline__ void mma16816(float* d, const uint32_t* a, uint32_t b0, uint32_t b1) {
    asm volatile(
        "mma.sync.aligned.m16n8k16.row.col.f32.f16.f16.f32 "
        "{%0,%1,%2,%3}, {%4,%5,%6,%7}, {%8,%9}, {%0,%1,%2,%3};"
        : "+f"(d[0]), "+f"(d[1]), "+f"(d[2]), "+f"(d[3])
        : "r"(a[0]), "r"(a[1]), "r"(a[2]), "r"(a[3]), "r"(b0), "r"(b1));
}
__device__ __forceinline__ uint32_t pack_half2(float a, float b) {
    __half2 h = __floats2half2_rn(a, b);
    return *reinterpret_cast<uint32_t*>(&h);
}

// ---------------------------------------------------------------------------
// fp32 -> (hi, lo) fp16 split  /  hi-only variant for weights
// ---------------------------------------------------------------------------
__global__ __launch_bounds__(256) void split_kernel(
    const float4* __restrict__ x, __half2* __restrict__ hi,
    __half2* __restrict__ lo, int n4)
{
    int i = blockIdx.x * 256 + threadIdx.x;
    if (i >= n4) return;
    float4 v = x[i];
    __half h0 = __float2half_rn(v.x), h1 = __float2half_rn(v.y);
    __half h2 = __float2half_rn(v.z), h3 = __float2half_rn(v.w);
    hi[2*i]   = __half2(h0, h1);
    hi[2*i+1] = __half2(h2, h3);
    lo[2*i]   = __half2(__float2half_rn(v.x - __half2float(h0)),
                        __float2half_rn(v.y - __half2float(h1)));
    lo[2*i+1] = __half2(__float2half_rn(v.z - __half2float(h2)),
                        __float2half_rn(v.w - __half2float(h3)));
}

__global__ __launch_bounds__(256) void split_hi_kernel(
    const float4* __restrict__ x, __half2* __restrict__ hi, int n4)
{
    int i = blockIdx.x * 256 + threadIdx.x;
    if (i >= n4) return;
    float4 v = x[i];
    hi[2*i]   = __half2(__float2half_rn(v.x), __float2half_rn(v.y));
    hi[2*i+1] = __half2(__float2half_rn(v.z), __float2half_rn(v.w));
}

// ---------------------------------------------------------------------------
// mma.sync split-fp16 GEMM: C[m,n] = bias[n] + sum_k A[m,k]*W[n,k], K=768
// D ~= Ah.Bh^T + Al.Bh^T (B hi only; 2 passes). 128x128 CTA tile, BK=32,
// 2-stage cp.async, 8 warps (2m x 4n). smem: 2 stages x 3 tiles x 10240B.
// ---------------------------------------------------------------------------
#define RS   80
#define TOFF 10240
#define SOFF 30720

__global__ __launch_bounds__(256, 2) void gemm_mma_split(
    const __half* __restrict__ Ahi, const __half* __restrict__ Alo,
    const __half* __restrict__ Bhi,
    const float* __restrict__ bias, float* __restrict__ C,
    __half* __restrict__ Chi, __half* __restrict__ Clo,
    int N, int do_split, int scale_cols)
{
    extern __shared__ char smem[];
    const uint32_t sb = smem_u32(smem);
    const int tid = threadIdx.x;
    const int wid = tid >> 5, lane = tid & 31;
    const int wm = wid & 1, wn = wid >> 1;
    const int m0 = blockIdx.y * 128;
    const int n0 = blockIdx.x * 128;

    const __half* srcs[3] = {Ahi, Alo, Bhi};
    const int r0s[3] = {m0, m0, n0};
    const int crow = tid >> 2;
    const int cc4  = tid & 3;

    float acc[4][4][4] = {};

    const int lrow  = ((lane >> 3) & 1) * 8 + (lane & 7);
    const int lkoff = (lane >> 4) * 16;
    const uint32_t a_base = sb + (uint32_t)(wm * 64 + lrow) * RS + lkoff;
    const uint32_t b_base = sb + (uint32_t)(wn * 32 + lrow) * RS + lkoff;

    {
        #pragma unroll
        for (int tI = 0; tI < 3; ++tI)
            #pragma unroll
            for (int it = 0; it < 2; ++it) {
                int row = crow + it * 64;
                cp_async16(sb + tI * TOFF + row * RS + cc4 * 16,
                           srcs[tI] + (size_t)(r0s[tI] + row) * D_ + cc4 * 8);
            }
        cp_commit();
    }

    for (int c = 0; c < 24; ++c) {
        if (c < 23) {
            const int k0 = (c + 1) * 32;
            const uint32_t base = sb + ((c + 1) & 1) * SOFF;
            #pragma unroll
            for (int tI = 0; tI < 3; ++tI)
                #pragma unroll
                for (int it = 0; it < 2; ++it) {
                    int row = crow + it * 64;
                    cp_async16(base + tI * TOFF + row * RS + cc4 * 16,
                               srcs[tI] + (size_t)(r0s[tI] + row) * D_ + k0 + cc4 * 8);
                }
            cp_commit();
            cp_wait1();
        } else {
            cp_wait0();
        }
        __syncthreads();

        const uint32_t st = ((uint32_t)(c & 1)) * SOFF;
        #pragma unroll
        for (int ks = 0; ks < 2; ++ks) {
            const uint32_t ko = ks * 32;
            uint32_t ah[4][4], al[4][4], bh[2][4];
            #pragma unroll
            for (int mi = 0; mi < 4; ++mi) {
                ldsm4(ah[mi], a_base + st + 0 * TOFF + mi * 16 * RS + ko);
                ldsm4(al[mi], a_base + st + 1 * TOFF + mi * 16 * RS + ko);
            }
            #pragma unroll
            for (int nt = 0; nt < 2; ++nt)
                ldsm4(bh[nt], b_base + st + 2 * TOFF + nt * 16 * RS + ko);
            #pragma unroll
            for (int mi = 0; mi < 4; ++mi)
                #pragma unroll
                for (int ni = 0; ni < 4; ++ni) {
                    const int nt = ni >> 1, hl = ni & 1;
                    mma16816(acc[mi][ni], ah[mi], bh[nt][hl], bh[nt][hl + 2]);
                    mma16816(acc[mi][ni], al[mi], bh[nt][hl], bh[nt][hl + 2]);
                }
        }
        __syncthreads();
    }

    const int g   = lane >> 2;
    const int tig = lane & 3;
    #pragma unroll
    for (int mi = 0; mi < 4; ++mi) {
        const int row = m0 + wm * 64 + mi * 16 + g;
        #pragma unroll
        for (int ni = 0; ni < 4; ++ni) {
            const int col = n0 + wn * 32 + ni * 8 + tig * 2;
            float b0v = bias[col], b1v = bias[col + 1];
            float v00 = acc[mi][ni][0] + b0v, v01 = acc[mi][ni][1] + b1v;
            float v10 = acc[mi][ni][2] + b0v, v11 = acc[mi][ni][3] + b1v;
            if (do_split) {
                const bool qreg = (col < scale_cols);   // q region: scale + lo needed
                float sc = qreg ? 0.125f : 1.0f;
                v00 *= sc; v01 *= sc; v10 *= sc; v11 *= sc;
                uint32_t h0 = pack_half2(v00, v01);
                uint32_t h1 = pack_half2(v10, v11);
                *reinterpret_cast<uint32_t*>(&Chi[(size_t)row * N + col]) = h0;
                *reinterpret_cast<uint32_t*>(&Chi[(size_t)(row + 8) * N + col]) = h1;
                if (qreg) {
                    __half2 h0b = *reinterpret_cast<__half2*>(&h0);
                    __half2 h1b = *reinterpret_cast<__half2*>(&h1);
                    uint32_t l0 = pack_half2(v00 - __half2float(h0b.x), v01 - __half2float(h0b.y));
                    uint32_t l1 = pack_half2(v10 - __half2float(h1b.x), v11 - __half2float(h1b.y));
                    *reinterpret_cast<uint32_t*>(&Clo[(size_t)row * N + col]) = l0;
                    *reinterpret_cast<uint32_t*>(&Clo[(size_t)(row + 8) * N + col]) = l1;
                }
            } else {
                float2 va = {v00, v01}, vb = {v10, v11};
                *reinterpret_cast<float2*>(&C[(size_t)row * N + col]) = va;
                *reinterpret_cast<float2*>(&C[(size_t)(row + 8) * N + col]) = vb;
            }
        }
    }
}

// ---------------------------------------------------------------------------
// Tensor-core flash attention, split-fp16 (A-side lo only).
// S = Qh.Kh + Ql.Kh ; softmax fp32 ; O += Ph.Vh + Pl.Vh.
// K and V are hi-only B operands.
// ---------------------------------------------------------------------------
#define ARS 144

__global__ __launch_bounds__(256) void attn_mma_kernel()
{
    extern __shared__ char smem[];
    const uint32_t sb = smem_u32(smem);
    const int tid = threadIdx.x, lane = tid & 31, wid = tid >> 5;
    const int qt = blockIdx.x, h = blockIdx.y, t = blockIdx.z;
    const int q0 = qt * 128;
    const size_t trow = (size_t)t * B_;

    const __half* qhg = g_qkv_hi + (trow + q0) * E3_ + h * HD_;
    const __half* qlg = g_qkv_lo + (trow + q0) * E3_ + h * HD_;
    const __half* khg0 = g_qkv_hi + trow * E3_ + D_ + h * HD_;
    const __half* vhg0 = g_qkv_hi + trow * E3_ + 2 * D_ + h * HD_;

    const int QH = 0, QL = 128 * ARS;
    const int KH = 0, VH = 64 * ARS;

    // stage Q (hi+lo)
    #pragma unroll
    for (int it = 0; it < 4; ++it) {
        int f = it * 256 + tid, r = f >> 3, c = f & 7;
        *(float4*)(smem + QH + r * ARS + c * 16) = *(const float4*)(qhg + (size_t)r * E3_ + c * 8);
        *(float4*)(smem + QL + r * ARS + c * 16) = *(const float4*)(qlg + (size_t)r * E3_ + c * 8);
    }
    __syncthreads();

    const int lrow  = ((lane >> 3) & 1) * 8 + (lane & 7);
    const int lkoff = (lane >> 4) * 16;
    uint32_t qfh[4][4], qfl[4][4];
    {
        const uint32_t qa = sb + (uint32_t)(wid * 16 + lrow) * ARS + lkoff;
        #pragma unroll
        for (int ks = 0; ks < 4; ++ks) {
            ldsm4(qfh[ks], qa + QH + ks * 32);
            ldsm4(qfl[ks], qa + QL + ks * 32);
        }
    }
    __syncthreads();

    float oacc[8][4] = {};
    float mr0 = -1e30f, mr1 = -1e30f, lr0 = 0.f, lr1 = 0.f;

    for (int kt = 0; kt < 8; ++kt) {
        const __half* khg = khg0 + (size_t)kt * 64 * E3_;
        const __half* vhg = vhg0 + (size_t)kt * 64 * E3_;

        // K hi tile (key-major rows)
        #pragma unroll
        for (int it = 0; it < 2; ++it) {
            int f = it * 256 + tid, r = f >> 3, c = f & 7;
            *(float4*)(smem + KH + r * ARS + c * 16) = *(const float4*)(khg + (size_t)r * E3_ + c * 8);
        }
        // V hi tile transposed to hd-major
        #pragma unroll
        for (int it = 0; it < 4; ++it) {
            int idx = it * 256 + tid, s = idx & 31, c = idx >> 5;
            uint32_t u0 = *(const uint32_t*)(vhg + (size_t)(2 * s) * E3_ + 2 * c);
            uint32_t u1 = *(const uint32_t*)(vhg + (size_t)(2 * s + 1) * E3_ + 2 * c);
            *(uint32_t*)(smem + VH + (2 * c) * ARS + s * 4)     = (u0 & 0xFFFFu) | (u1 << 16);
            *(uint32_t*)(smem + VH + (2 * c + 1) * ARS + s * 4) = (u0 >> 16) | (u1 & 0xFFFF0000u);
        }
        __syncthreads();

        // S = Q K^T (2 passes)
        float sacc[8][4] = {};
        #pragma unroll
        for (int ks = 0; ks < 4; ++ks) {
            uint32_t kfh[4][4];
            #pragma unroll
            for (int ng = 0; ng < 4; ++ng) {
                const uint32_t ka = sb + (uint32_t)(ng * 16 + lrow) * ARS + lkoff + ks * 32;
                ldsm4(kfh[ng], ka + KH);
            }
            #pragma unroll
            for (int ng = 0; ng < 4; ++ng)
                #pragma unroll
                for (int sub = 0; sub < 2; ++sub) {
                    const int ni = ng * 2 + sub;
                    mma16816(sacc[ni], qfh[ks], kfh[ng][sub], kfh[ng][sub + 2]);
                    mma16816(sacc[ni], qfl[ks], kfh[ng][sub], kfh[ng][sub + 2]);
                }
        }

        // online softmax
        float mx0 = -1e30f, mx1 = -1e30f;
        #pragma unroll
        for (int ni = 0; ni < 8; ++ni) {
            mx0 = fmaxf(mx0, fmaxf(sacc[ni][0], sacc[ni][1]));
            mx1 = fmaxf(mx1, fmaxf(sacc[ni][2], sacc[ni][3]));
        }
        mx0 = fmaxf(mx0, __shfl_xor_sync(0xffffffffu, mx0, 1));
        mx0 = fmaxf(mx0, __shfl_xor_sync(0xffffffffu, mx0, 2));
        mx1 = fmaxf(mx1, __shfl_xor_sync(0xffffffffu, mx1, 1));
        mx1 = fmaxf(mx1, __shfl_xor_sync(0xffffffffu, mx1, 2));
        const float nm0 = fmaxf(mr0, mx0), nm1 = fmaxf(mr1, mx1);
        const float a0 = __expf(mr0 - nm0), a1 = __expf(mr1 - nm1);
        mr0 = nm0; mr1 = nm1;

        uint32_t phA[8], phB[8], plA[8], plB[8];
        float rs0 = 0.f, rs1 = 0.f;
        #pragma unroll
        for (int ni = 0; ni < 8; ++ni) {
            float e0 = __expf(sacc[ni][0] - nm0), e1 = __expf(sacc[ni][1] - nm0);
            float e2 = __expf(sacc[ni][2] - nm1), e3 = __expf(sacc[ni][3] - nm1);
            rs0 += e0 + e1; rs1 += e2 + e3;
            uint32_t hA = pack_half2(e0, e1), hB = pack_half2(e2, e3);
            __half2 hAb = *reinterpret_cast<__half2*>(&hA);
            __half2 hBb = *reinterpret_cast<__half2*>(&hB);
            phA[ni] = hA; phB[ni] = hB;
            plA[ni] = pack_half2(e0 - __half2float(hAb.x), e1 - __half2float(hAb.y));
            plB[ni] = pack_half2(e2 - __half2float(hBb.x), e3 - __half2float(hBb.y));
            oacc[ni][0] *= a0; oacc[ni][1] *= a0;
            oacc[ni][2] *= a1; oacc[ni][3] *= a1;
        }
        rs0 += __shfl_xor_sync(0xffffffffu, rs0, 1);
        rs0 += __shfl_xor_sync(0xffffffffu, rs0, 2);
        rs1 += __shfl_xor_sync(0xffffffffu, rs1, 1);
        rs1 += __shfl_xor_sync(0xffffffffu, rs1, 2);
        lr0 = lr0 * a0 + rs0;
        lr1 = lr1 * a1 + rs1;

        // O += P V (2 passes)
        #pragma unroll
        for (int j = 0; j < 4; ++j) {
            uint32_t vfh[4][4];
            #pragma unroll
            for (int ng = 0; ng < 4; ++ng) {
                const uint32_t va = sb + (uint32_t)(ng * 16 + lrow) * ARS + lkoff + j * 32;
                ldsm4(vfh[ng], va + VH);
            }
            uint32_t aph[4] = {phA[2*j], phB[2*j], phA[2*j+1], phB[2*j+1]};
            uint32_t apl[4] = {plA[2*j], plB[2*j], plA[2*j+1], plB[2*j+1]};
            #pragma unroll
            for (int ng = 0; ng < 4; ++ng)
                #pragma unroll
                for (int sub = 0; sub < 2; ++sub) {
                    const int ni = ng * 2 + sub;
                    mma16816(oacc[ni], aph, vfh[ng][sub], vfh[ng][sub + 2]);
                    mma16816(oacc[ni], apl, vfh[ng][sub], vfh[ng][sub + 2]);
                }
        }
        __syncthreads();
    }

    // epilogue: normalize by l, write ctx hi/lo fp16
    const float inv0 = 1.f / lr0, inv1 = 1.f / lr1;
    const int r0 = q0 + wid * 16 + (lane >> 2);
    const int col0 = h * HD_ + (lane & 3) * 2;
    __half* chg = g_ctx_hi + (trow + r0) * D_ + col0;
    __half* clg = g_ctx_lo + (trow + r0) * D_ + col0;
    #pragma unroll
    for (int ni = 0; ni < 8; ++ni) {
        float v0 = oacc[ni][0] * inv0, v1 = oacc[ni][1] * inv0;
        float v2 = oacc[ni][2] * inv1, v3 = oacc[ni][3] * inv1;
        uint32_t h0 = pack_half2(v0, v1), h1 = pack_half2(v2, v3);
        __half2 h0b = *reinterpret_cast<__half2*>(&h0);
        __half2 h1b = *reinterpret_cast<__half2*>(&h1);
        uint32_t l0 = pack_half2(v0 - __half2float(h0b.x), v1 - __half2float(h0b.y));
        uint32_t l1 = pack_half2(v2 - __half2float(h1b.x), v3 - __half2float(h1b.y));
        *reinterpret_cast<uint32_t*>(chg + ni * 8) = h0;
        *reinterpret_cast<uint32_t*>(chg + 8 * D_ + ni * 8) = h1;
        *reinterpret_cast<uint32_t*>(clg + ni * 8) = l0;
        *reinterpret_cast<uint32_t*>(clg + 8 * D_ + ni * 8) = l1;
    }
}

// ---------------------------------------------------------------------------
// Epilogue reductions
// ---------------------------------------------------------------------------
__device__ __forceinline__ float block_reduce_sum(float v, float* sbuf)
{
    int lane = threadIdx.x & 31, w = threadIdx.x >> 5;
    #pragma unroll
    for (int o = 16; o; o >>= 1) v += __shfl_xor_sync(0xffffffffu, v, o);
    if (lane == 0) sbuf[w] = v;
    __syncthreads();
    float s = (threadIdx.x < (blockDim.x >> 5)) ? sbuf[threadIdx.x] : 0.f;
    if (w == 0) {
        #pragma unroll
        for (int o = 4; o; o >>= 1) s += __shfl_xor_sync(0xffffffffu, s, o);
        if (lane == 0) sbuf[0] = s;
    }
    __syncthreads();
    return sbuf[0];
}

__global__ __launch_bounds__(256) void normalize_kernel()
{
    __shared__ float sbuf[32];
    int row = blockIdx.x;
    float* x = g_out + (size_t)row * D_;
    float s = 0.f;
    for (int i = threadIdx.x; i < D_; i += 256) { float v = x[i]; s += v * v; }
    s = block_reduce_sum(s, sbuf);
    float inv = 1.f / fmaxf(sqrtf(s), 1e-8f);
    for (int i = threadIdx.x; i < D_; i += 256) x[i] *= inv;
}

__global__ __launch_bounds__(256) void mean_kernel()
{
    int t = blockIdx.y;
    int d = blockIdx.x * 256 + threadIdx.x;
    const float* base = g_out + (size_t)t * B_ * D_ + d;
    float s = 0.f;
    for (int b = 0; b < B_; ++b) s += base[(size_t)b * D_];
    g_mean[t * D_ + d] = s * (1.f / B_);
}

__global__ __launch_bounds__(256) void adj_kernel(float* __restrict__ outp)
{
    __shared__ float sbuf[32];
    int row = blockIdx.x;
    int t = row / B_;
    const float* x = g_out + (size_t)row * D_;
    const float* m = g_mean + t * D_;
    float s = 0.f;
    for (int i = threadIdx.x; i < D_; i += 256) s += x[i] * m[i];
    s = block_reduce_sum(s, sbuf);
    if (threadIdx.x == 0) outp[row] = s;
}

// ---------------------------------------------------------------------------

extern "C" void kernel_launch(void* const* d_in, const int* in_sizes, int n_in,
                              void* d_out, int out_size)
{
    const float* node = (const float*)d_in[0];
    const float* w1   = (const float*)d_in[1];
    const float* b1   = (const float*)d_in[2];
    const float* w2   = (const float*)d_in[3];
    const float* b2   = (const float*)d_in[4];
    float* outp = (float*)d_out;

    float* outb;
    cudaGetSymbolAddress((void**)&outb, g_out);
    __half *qh, *ql, *nh, *nl, *ch, *cl, *w1h, *w2h;
    cudaGetSymbolAddress((void**)&qh,  g_qkv_hi);
    cudaGetSymbolAddress((void**)&ql,  g_qkv_lo);
    cudaGetSymbolAddress((void**)&nh,  g_node_hi);
    cudaGetSymbolAddress((void**)&nl,  g_node_lo);
    cudaGetSymbolAddress((void**)&ch,  g_ctx_hi);
    cudaGetSymbolAddress((void**)&cl,  g_ctx_lo);
    cudaGetSymbolAddress((void**)&w1h, g_w1_hi);
    cudaGetSymbolAddress((void**)&w2h, g_w2_hi);

    const int gemm_smem = 2 * SOFF;            // 61440 B
    const int attn_smem = 2 * 128 * ARS;       // 36864 B
    cudaFuncSetAttribute(gemm_mma_split, cudaFuncAttributeMaxDynamicSharedMemorySize, gemm_smem);
    cudaFuncSetAttribute(attn_mma_kernel, cudaFuncAttributeMaxDynamicSharedMemorySize, attn_smem);

    // split inputs (node: hi+lo, weights: hi only)
    {
        int n4 = NROWS * D_ / 4;
        split_kernel<<<(n4 + 255)/256, 256>>>((const float4*)node,
            (__half2*)nh, (__half2*)nl, n4);
        int w14 = E3_ * D_ / 4;
        split_hi_kernel<<<(w14 + 255)/256, 256>>>((const float4*)w1, (__half2*)w1h, w14);
        int w24 = D_ * D_ / 4;
        split_hi_kernel<<<(w24 + 255)/256, 256>>>((const float4*)w2, (__half2*)w2h, w24);
    }

    // 1. QKV projection -> fp16 hi qkv (+lo for q cols, q pre-scaled 0.125)
    gemm_mma_split<<<dim3(E3_/128, NROWS/128), 256, gemm_smem>>>(
        nh, nl, w1h, b1, nullptr, qh, ql, E3_, 1, D_);

    // 2. Tensor-core flash attention -> ctx fp16 hi/lo
    attn_mma_kernel<<<dim3(B_/128, H_, T_), 256, attn_smem>>>();

    // 3. Out projection -> fp32 g_out
    gemm_mma_split<<<dim3(D_/128, NROWS/128), 256, gemm_smem>>>(
        ch, cl, w2h, b2, outb, nullptr, nullptr, D_, 0, 0);

    // 4. Epilogue
    normalize_kernel<<<NROWS, 256>>>();
    mean_kernel<<<dim3(D_/256, T_), 256>>>();
    adj_kernel<<<NROWS, 256>>>(outp);
}